// round 5
// baseline (speedup 1.0000x reference)
#include <cuda_runtime.h>
#include <math.h>

// Problem constants
#define B_   1024
#define T_   64
#define H_   512
#define V_   1024
#define GEN_ 100
#define H4_  2048
#define NBLK 128

typedef unsigned long long ull;

// Persistent state (device globals — no allocation allowed)
__device__ float d_hbuf[2][B_ * H_];   // ping-pong hidden state
__device__ float d_c[B_ * H_];         // cell state
__device__ float d_bias[H4_];          // b_ih + b_hh
__device__ int   d_tok[B_];            // current token per batch row
__device__ unsigned d_bar_count = 0;   // grid barrier
__device__ unsigned d_bar_gen   = 0;

__device__ __forceinline__ float sigm(float x) { return 1.0f / (1.0f + expf(-x)); }

__device__ __forceinline__ ull dup2(float x) {
    ull r; asm("mov.b64 %0, {%1, %1};" : "=l"(r) : "f"(x)); return r;
}
__device__ __forceinline__ void ffma2(ull& d, ull a, ull b) {
    asm("fma.rn.f32x2 %0, %1, %2, %0;" : "+l"(d) : "l"(a), "l"(b));
}
__device__ __forceinline__ float2 unp2(ull v) {
    float2 f; asm("mov.b64 {%0, %1}, %2;" : "=f"(f.x), "=f"(f.y) : "l"(v)); return f;
}

// Software grid barrier: all NBLK blocks are co-resident (1 block/SM).
__device__ __forceinline__ void grid_barrier() {
    __threadfence();
    __syncthreads();
    if (threadIdx.x == 0) {
        const unsigned gen = *((volatile unsigned*)&d_bar_gen);
        if (atomicAdd(&d_bar_count, 1u) == NBLK - 1) {
            d_bar_count = 0;
            __threadfence();
            *((volatile unsigned*)&d_bar_gen) = gen + 1;
        } else {
            while (*((volatile unsigned*)&d_bar_gen) == gen) { }
        }
    }
    __syncthreads();
}

// ---------------------------------------------------------------------------
// init: h0/c0 = input*W + b ; bias = b_ih + b_hh ; tok0 from onehots[:,0,:]
// ---------------------------------------------------------------------------
__global__ void init_kernel(const float* __restrict__ input,
                            const float* __restrict__ onehots,
                            const float* __restrict__ Wh, const float* __restrict__ bh,
                            const float* __restrict__ Wc, const float* __restrict__ bc,
                            const float* __restrict__ b_ih, const float* __restrict__ b_hh)
{
    const int b = blockIdx.x;
    const int tid = threadIdx.x;
    const float xv = input[b];

    for (int i = tid; i < H_; i += 256) {
        d_hbuf[0][b * H_ + i] = xv * Wh[i] + bh[i];
        d_c[b * H_ + i]       = xv * Wc[i] + bc[i];
    }
    if (b < H4_ / 256) {
        const int j = b * 256 + tid;
        d_bias[j] = b_ih[j] + b_hh[j];
    }
    const float* oh = onehots + (size_t)b * T_ * V_;
    for (int v = tid; v < V_; v += 256)
        if (oh[v] > 0.5f) d_tok[b] = v;
}

// ---------------------------------------------------------------------------
// Persistent kernel: 64 x (gates phase | barrier | head phase | barrier).
// 128 blocks x 256 threads, one block per SM (all co-resident).
// ---------------------------------------------------------------------------
__global__ void __launch_bounds__(256)
lstm_persistent_kernel(const float* __restrict__ Whh,
                       const float* __restrict__ Wih,
                       const float* __restrict__ W1, const float* __restrict__ b1,
                       const float* __restrict__ W2, const float* __restrict__ b2,
                       float* __restrict__ out)
{
    __shared__ __align__(16) char smem[36992];
    // gates view
    float (*hsm)[132] = (float (*)[132])smem;            // 16x132 = 8448 B
    float (*wsm)[132] = (float (*)[132])(smem + 8448);   // 16x132 = 8448 B
    // head view (union; phases separated by grid barriers)
    float* sbuf = (float*)smem;                          // 8x1024 = 32768 B
    float (*z1s)[104] = (float (*)[104])(smem + 32768);  // 3328 B
    float* lse_s = (float*)(smem + 32768 + 3328);        // 32 B

    const int tid = threadIdx.x;
    const int blk = blockIdx.x;

    // gates-tile coordinates
    const int gbx = blk & 7;            // b-tile (128 rows)
    const int gby = blk >> 3;           // h-tile (32 cols)
    const int b0g = gbx * 128;
    const int h0g = gby * 32;
    const int tx = tid & 15;            // 2-h-column group
    const int ty = tid >> 4;            // 8-b-row group

    // gates loader jobs (two float4 jobs per thread)
    const int r0 = tid >> 2,          kq0 = (tid & 3) * 4;
    const int r1 = (tid + 256) >> 2,  kq1 = ((tid + 256) & 3) * 4;
    const int wrow0 = (r0 >> 5) * H_ + h0g + (r0 & 31);
    const int wrow1 = (r1 >> 5) * H_ + h0g + (r1 & 31);
    const float* wb0 = Whh + (size_t)wrow0 * H_ + kq0;
    const float* wb1 = Whh + (size_t)wrow1 * H_ + kq1;

    // head coordinates
    const int b0h = blk * 8;
    const int w = tid >> 5, lane = tid & 31;

    int par = 0;
    for (int t = 0; t < T_; t++) {
        // ================= gates phase =================
        {
            const float* __restrict__ hin  = d_hbuf[par];
            float* __restrict__       hout = d_hbuf[par ^ 1];
            const float* hb0 = hin + (size_t)(b0g + r0) * H_ + kq0;
            const float* hb1 = hin + (size_t)(b0g + r1) * H_ + kq1;

            ull acc2[8][4];
#pragma unroll
            for (int u = 0; u < 8; u++)
#pragma unroll
                for (int j = 0; j < 4; j++) acc2[u][j] = 0ull;

            float4 ph0 = *(const float4*)(hb0);
            float4 ph1 = *(const float4*)(hb1);
            float4 pw0 = *(const float4*)(wb0);
            float4 pw1 = *(const float4*)(wb1);

            for (int k0 = 0; k0 < H_; k0 += 16) {
                hsm[kq0 + 0][r0] = ph0.x; hsm[kq0 + 1][r0] = ph0.y;
                hsm[kq0 + 2][r0] = ph0.z; hsm[kq0 + 3][r0] = ph0.w;
                hsm[kq1 + 0][r1] = ph1.x; hsm[kq1 + 1][r1] = ph1.y;
                hsm[kq1 + 2][r1] = ph1.z; hsm[kq1 + 3][r1] = ph1.w;
                wsm[kq0 + 0][r0] = pw0.x; wsm[kq0 + 1][r0] = pw0.y;
                wsm[kq0 + 2][r0] = pw0.z; wsm[kq0 + 3][r0] = pw0.w;
                wsm[kq1 + 0][r1] = pw1.x; wsm[kq1 + 1][r1] = pw1.y;
                wsm[kq1 + 2][r1] = pw1.z; wsm[kq1 + 3][r1] = pw1.w;
                __syncthreads();

                if (k0 + 16 < H_) {
                    ph0 = *(const float4*)(hb0 + k0 + 16);
                    ph1 = *(const float4*)(hb1 + k0 + 16);
                    pw0 = *(const float4*)(wb0 + k0 + 16);
                    pw1 = *(const float4*)(wb1 + k0 + 16);
                }

#pragma unroll
                for (int kk = 0; kk < 16; kk++) {
                    const float4 a0 = *(const float4*)&hsm[kk][ty * 8];
                    const float4 a1 = *(const float4*)&hsm[kk][ty * 8 + 4];
                    const ull w0 = *(const ull*)&wsm[kk][      tx * 2];
                    const ull w1 = *(const ull*)&wsm[kk][32  + tx * 2];
                    const ull w2 = *(const ull*)&wsm[kk][64  + tx * 2];
                    const ull w3 = *(const ull*)&wsm[kk][96  + tx * 2];
                    const float hv[8] = {a0.x, a0.y, a0.z, a0.w, a1.x, a1.y, a1.z, a1.w};
#pragma unroll
                    for (int u = 0; u < 8; u++) {
                        const ull h2 = dup2(hv[u]);
                        ffma2(acc2[u][0], h2, w0);
                        ffma2(acc2[u][1], h2, w1);
                        ffma2(acc2[u][2], h2, w2);
                        ffma2(acc2[u][3], h2, w3);
                    }
                }
                __syncthreads();
            }

            // fused LSTM cell epilogue
            const int hbase = h0g + tx * 2;
            float bb[8];
#pragma unroll
            for (int q = 0; q < 4; q++) {
                bb[q * 2 + 0] = d_bias[q * H_ + hbase + 0];
                bb[q * 2 + 1] = d_bias[q * H_ + hbase + 1];
            }
#pragma unroll
            for (int u = 0; u < 8; u++) {
                const int b = b0g + ty * 8 + u;
                const int tok = d_tok[b];
                const float2 cold = *(const float2*)&d_c[b * H_ + hbase];
                const float2 g0 = unp2(acc2[u][0]);   // gate i, cols {0,1}
                const float2 g1 = unp2(acc2[u][1]);   // gate f
                const float2 g2 = unp2(acc2[u][2]);   // gate g
                const float2 g3 = unp2(acc2[u][3]);   // gate o
                const float gacc[4][2] = {{g0.x, g0.y}, {g1.x, g1.y}, {g2.x, g2.y}, {g3.x, g3.y}};
                float2 cnew, hnew;
#pragma unroll
                for (int jj = 0; jj < 2; jj++) {
                    const int hcol = hbase + jj;
                    const float gi = gacc[0][jj] + __ldg(&Wih[(size_t)(0 * H_ + hcol) * V_ + tok]) + bb[0 + jj];
                    const float gf = gacc[1][jj] + __ldg(&Wih[(size_t)(1 * H_ + hcol) * V_ + tok]) + bb[2 + jj];
                    const float gg = gacc[2][jj] + __ldg(&Wih[(size_t)(2 * H_ + hcol) * V_ + tok]) + bb[4 + jj];
                    const float go = gacc[3][jj] + __ldg(&Wih[(size_t)(3 * H_ + hcol) * V_ + tok]) + bb[6 + jj];
                    const float co = (jj == 0) ? cold.x : cold.y;
                    const float cn = sigm(gf) * co + sigm(gi) * tanhf(gg);
                    const float hn = sigm(go) * tanhf(cn);
                    if (jj == 0) { cnew.x = cn; hnew.x = hn; }
                    else         { cnew.y = cn; hnew.y = hn; }
                }
                *(float2*)&d_c[b * H_ + hbase]  = cnew;
                *(float2*)&hout[b * H_ + hbase] = hnew;
            }
        }
        grid_barrier();

        // ================= head phase =================
        {
            const float* __restrict__ hbuf = d_hbuf[par ^ 1];

            // load 8x512 h rows
            {
                float4* sb4 = (float4*)sbuf;
                const float4* hb4 = (const float4*)(hbuf + (size_t)b0h * H_);
                for (int i = tid; i < 8 * H_ / 4; i += 256) sb4[i] = hb4[i];
            }
            __syncthreads();

            // z1: warp per output column g, 8 batch accumulators
            for (int g = w; g < GEN_; g += 8) {
                float a[8];
#pragma unroll
                for (int bi = 0; bi < 8; bi++) a[bi] = 0.f;
                const float4* wp = (const float4*)(W1 + (size_t)g * H_);
#pragma unroll
                for (int p = 0; p < 4; p++) {
                    const float4 wv = wp[p * 32 + lane];
#pragma unroll
                    for (int bi = 0; bi < 8; bi++) {
                        const float4 hv = *(const float4*)&sbuf[bi * H_ + (p * 32 + lane) * 4];
                        a[bi] += wv.x * hv.x + wv.y * hv.y + wv.z * hv.z + wv.w * hv.w;
                    }
                }
#pragma unroll
                for (int bi = 0; bi < 8; bi++) {
#pragma unroll
                    for (int off = 16; off; off >>= 1)
                        a[bi] += __shfl_down_sync(0xffffffffu, a[bi], off);
                }
                if (lane == 0) {
                    const float bv = b1[g];
#pragma unroll
                    for (int bi = 0; bi < 8; bi++)
                        z1s[bi][g] = fmaxf(a[bi] + bv, 0.f);
                }
            }
            __syncthreads();   // h dead; sbuf becomes z2

            float (*z2s)[1024] = (float (*)[1024])sbuf;
#pragma unroll
            for (int vc = 0; vc < 4; vc++) {
                const int v = vc * 256 + tid;
                float acc[8];
#pragma unroll
                for (int bi = 0; bi < 8; bi++) acc[bi] = 0.f;
                const float4* wp = (const float4*)(W2 + (size_t)v * GEN_);
#pragma unroll
                for (int k4 = 0; k4 < GEN_ / 4; k4++) {
                    const float4 wv = wp[k4];
#pragma unroll
                    for (int bi = 0; bi < 8; bi++) {
                        const float4 z = *(const float4*)&z1s[bi][k4 * 4];
                        acc[bi] += wv.x * z.x + wv.y * z.y + wv.z * z.z + wv.w * z.w;
                    }
                }
                const float bv = b2[v];
#pragma unroll
                for (int bi = 0; bi < 8; bi++) z2s[bi][v] = acc[bi] + bv;
            }
            __syncthreads();

            // per-warp reduction: warp w owns batch row b0h+w
            {
                float m = -3.0e38f; int mi = 0;
                for (int v = lane; v < V_; v += 32) {
                    const float x = z2s[w][v];
                    if (x > m) { m = x; mi = v; }
                }
#pragma unroll
                for (int off = 16; off; off >>= 1) {
                    const float om  = __shfl_down_sync(0xffffffffu, m, off);
                    const int   omi = __shfl_down_sync(0xffffffffu, mi, off);
                    if (om > m || (om == m && omi < mi)) { m = om; mi = omi; }
                }
                m  = __shfl_sync(0xffffffffu, m, 0);
                mi = __shfl_sync(0xffffffffu, mi, 0);

                float s = 0.f;
                for (int v = lane; v < V_; v += 32) s += expf(z2s[w][v] - m);
#pragma unroll
                for (int off = 16; off; off >>= 1) s += __shfl_down_sync(0xffffffffu, s, off);

                if (lane == 0) {
                    lse_s[w] = m + logf(s);
                    d_tok[b0h + w] = mi;
                }
            }
            __syncthreads();

            float* orow = out + (size_t)t * B_ * V_ + (size_t)b0h * V_;
            for (int i = tid; i < 8 * V_ / 4; i += 256) {
                const int bi = i >> 8;
                float4 v4 = *(const float4*)&z2s[bi][(i & 255) * 4];
                const float l = lse_s[bi];
                v4.x -= l; v4.y -= l; v4.z -= l; v4.w -= l;
                *(float4*)&orow[i * 4] = v4;
            }
        }
        grid_barrier();

        par ^= 1;
    }
}

// ---------------------------------------------------------------------------
// kernel_launch: 2 graph nodes (init + persistent loop)
// ---------------------------------------------------------------------------
extern "C" void kernel_launch(void* const* d_in, const int* in_sizes, int n_in,
                              void* d_out, int out_size)
{
    const float* input   = (const float*)d_in[0];
    const float* onehots = (const float*)d_in[1];
    const float* Wh   = (const float*)d_in[4];
    const float* bh   = (const float*)d_in[5];
    const float* Wc   = (const float*)d_in[6];
    const float* bc   = (const float*)d_in[7];
    const float* W_ih = (const float*)d_in[8];
    const float* W_hh = (const float*)d_in[9];
    const float* b_ih = (const float*)d_in[10];
    const float* b_hh = (const float*)d_in[11];
    const float* W1   = (const float*)d_in[12];
    const float* b1   = (const float*)d_in[13];
    const float* W2   = (const float*)d_in[14];
    const float* b2   = (const float*)d_in[15];
    float* out = (float*)d_out;

    init_kernel<<<B_, 256>>>(input, onehots, Wh, bh, Wc, bc, b_ih, b_hh);
    lstm_persistent_kernel<<<NBLK, 256>>>(W_hh, W_ih, W1, b1, W2, b2, out);
}

// round 6
// speedup vs baseline: 1.1517x; 1.1517x over previous
#include <cuda_runtime.h>
#include <math.h>

// Problem constants
#define B_   1024
#define T_   64
#define H_   512
#define V_   1024
#define GEN_ 100
#define H4_  2048
#define NGATES 128
#define NHEAD  128
#define NTOT   256

typedef unsigned long long ull;

// Persistent state (device globals — no allocation allowed)
__device__ float d_hbuf[2][B_ * H_];   // ping-pong hidden state
__device__ float d_c[B_ * H_];         // cell state
__device__ float d_bias[H4_];          // b_ih + b_hh
__device__ int   d_tok[B_];            // current token per batch row
__device__ unsigned d_bar_count;       // 256-block stage barrier
__device__ unsigned d_bar_gen;
__device__ unsigned d_tok_cnt;         // head-completion counter (tok published)
__device__ unsigned d_tok_gen;         // == number of completed head steps

__device__ __forceinline__ float sigm(float x) { return 1.0f / (1.0f + expf(-x)); }

__device__ __forceinline__ ull dup2(float x) {
    ull r; asm("mov.b64 %0, {%1, %1};" : "=l"(r) : "f"(x)); return r;
}
__device__ __forceinline__ void ffma2(ull& d, ull a, ull b) {
    asm("fma.rn.f32x2 %0, %1, %2, %0;" : "+l"(d) : "l"(a), "l"(b));
}
__device__ __forceinline__ float2 unp2(ull v) {
    float2 f; asm("mov.b64 {%0, %1}, %2;" : "=f"(f.x), "=f"(f.y) : "l"(v)); return f;
}

// Stage barrier across all NTOT blocks (all co-resident: 256 <= 2*148 CTAs).
__device__ __forceinline__ void stage_barrier() {
    __threadfence();
    __syncthreads();
    if (threadIdx.x == 0) {
        const unsigned gen = *((volatile unsigned*)&d_bar_gen);
        if (atomicAdd(&d_bar_count, 1u) == NTOT - 1) {
            d_bar_count = 0;
            __threadfence();
            *((volatile unsigned*)&d_bar_gen) = gen + 1;
        } else {
            while (*((volatile unsigned*)&d_bar_gen) == gen) { __nanosleep(32); }
        }
    }
    __syncthreads();
}

// ---------------------------------------------------------------------------
// init: h0/c0 = input*W + b ; bias = b_ih + b_hh ; tok0 ; reset sync counters
// ---------------------------------------------------------------------------
__global__ void init_kernel(const float* __restrict__ input,
                            const float* __restrict__ onehots,
                            const float* __restrict__ Wh, const float* __restrict__ bh,
                            const float* __restrict__ Wc, const float* __restrict__ bc,
                            const float* __restrict__ b_ih, const float* __restrict__ b_hh)
{
    const int b = blockIdx.x;
    const int tid = threadIdx.x;
    const float xv = input[b];

    if (b == 0 && tid == 0) {
        d_bar_count = 0; d_bar_gen = 0; d_tok_cnt = 0; d_tok_gen = 0;
    }
    for (int i = tid; i < H_; i += 256) {
        d_hbuf[0][b * H_ + i] = xv * Wh[i] + bh[i];
        d_c[b * H_ + i]       = xv * Wc[i] + bc[i];
    }
    if (b < H4_ / 256) {
        const int j = b * 256 + tid;
        d_bias[j] = b_ih[j] + b_hh[j];
    }
    const float* oh = onehots + (size_t)b * T_ * V_;
    for (int v = tid; v < V_; v += 256)
        if (oh[v] > 0.5f) d_tok[b] = v;
}

// ---------------------------------------------------------------------------
// Pipelined persistent kernel.
// Blocks 0..127: gates role.  Blocks 128..255: head role.  2 CTAs/SM.
// Stage s: gates step s  ||  head step s-1.   65 stages, barrier between.
// Gates step s epilogue waits for tok_gen >= s (published mid-stage by head).
// ---------------------------------------------------------------------------
__global__ void __launch_bounds__(256, 2)
lstm_pipeline_kernel(const float* __restrict__ Whh,
                     const float* __restrict__ Wih,
                     const float* __restrict__ W1, const float* __restrict__ b1,
                     const float* __restrict__ W2, const float* __restrict__ b2,
                     float* __restrict__ out)
{
    __shared__ __align__(16) char smem[36160];
    const int tid = threadIdx.x;
    const int blk = blockIdx.x;

    if (blk < NGATES) {
        // ==================== GATES ROLE ====================
        float (*hsm)[132] = (float (*)[132])smem;            // 16x132
        float (*wsm)[132] = (float (*)[132])(smem + 8448);   // 16x132

        const int gbx = blk & 7;            // b-tile (128 rows)
        const int gby = blk >> 3;           // h-tile (32 cols)
        const int b0g = gbx * 128;
        const int h0g = gby * 32;
        const int tx = tid & 15;            // 2-h-column group
        const int ty = tid >> 4;            // 8-b-row group

        const int r0 = tid >> 2,          kq0 = (tid & 3) * 4;
        const int r1 = (tid + 256) >> 2,  kq1 = ((tid + 256) & 3) * 4;
        const int wrow0 = (r0 >> 5) * H_ + h0g + (r0 & 31);
        const int wrow1 = (r1 >> 5) * H_ + h0g + (r1 & 31);
        const float* wb0 = Whh + (size_t)wrow0 * H_ + kq0;
        const float* wb1 = Whh + (size_t)wrow1 * H_ + kq1;

        for (int t = 0; t < T_; t++) {
            const int par = t & 1;
            const float* __restrict__ hin  = d_hbuf[par];
            float* __restrict__       hout = d_hbuf[par ^ 1];
            const float4* hb0 = (const float4*)(hin + (size_t)(b0g + r0) * H_ + kq0);
            const float4* hb1 = (const float4*)(hin + (size_t)(b0g + r1) * H_ + kq1);

            ull acc2[8][4];
#pragma unroll
            for (int u = 0; u < 8; u++)
#pragma unroll
                for (int j = 0; j < 4; j++) acc2[u][j] = 0ull;

            float4 ph0 = __ldcg(hb0);
            float4 ph1 = __ldcg(hb1);
            float4 pw0 = *(const float4*)(wb0);
            float4 pw1 = *(const float4*)(wb1);

            for (int k0 = 0; k0 < H_; k0 += 16) {
                hsm[kq0 + 0][r0] = ph0.x; hsm[kq0 + 1][r0] = ph0.y;
                hsm[kq0 + 2][r0] = ph0.z; hsm[kq0 + 3][r0] = ph0.w;
                hsm[kq1 + 0][r1] = ph1.x; hsm[kq1 + 1][r1] = ph1.y;
                hsm[kq1 + 2][r1] = ph1.z; hsm[kq1 + 3][r1] = ph1.w;
                wsm[kq0 + 0][r0] = pw0.x; wsm[kq0 + 1][r0] = pw0.y;
                wsm[kq0 + 2][r0] = pw0.z; wsm[kq0 + 3][r0] = pw0.w;
                wsm[kq1 + 0][r1] = pw1.x; wsm[kq1 + 1][r1] = pw1.y;
                wsm[kq1 + 2][r1] = pw1.z; wsm[kq1 + 3][r1] = pw1.w;
                __syncthreads();

                if (k0 + 16 < H_) {
                    ph0 = __ldcg(hb0 + (k0 + 16) / 4);
                    ph1 = __ldcg(hb1 + (k0 + 16) / 4);
                    pw0 = *(const float4*)(wb0 + k0 + 16);
                    pw1 = *(const float4*)(wb1 + k0 + 16);
                }

#pragma unroll
                for (int kk = 0; kk < 16; kk++) {
                    const float4 a0 = *(const float4*)&hsm[kk][ty * 8];
                    const float4 a1 = *(const float4*)&hsm[kk][ty * 8 + 4];
                    const ull w0 = *(const ull*)&wsm[kk][      tx * 2];
                    const ull w1 = *(const ull*)&wsm[kk][32  + tx * 2];
                    const ull w2 = *(const ull*)&wsm[kk][64  + tx * 2];
                    const ull w3 = *(const ull*)&wsm[kk][96  + tx * 2];
                    const float hv[8] = {a0.x, a0.y, a0.z, a0.w, a1.x, a1.y, a1.z, a1.w};
#pragma unroll
                    for (int u = 0; u < 8; u++) {
                        const ull h2 = dup2(hv[u]);
                        ffma2(acc2[u][0], h2, w0);
                        ffma2(acc2[u][1], h2, w1);
                        ffma2(acc2[u][2], h2, w2);
                        ffma2(acc2[u][3], h2, w3);
                    }
                }
                __syncthreads();
            }

            // wait for tok_{t-1} (published by head step t-1, same stage)
            if (t > 0) {
                if (tid == 0) {
                    while (*((volatile unsigned*)&d_tok_gen) < (unsigned)t) { __nanosleep(32); }
                }
                __syncthreads();
            }

            // fused LSTM cell epilogue
            const int hbase = h0g + tx * 2;
            float bb[8];
#pragma unroll
            for (int q = 0; q < 4; q++) {
                bb[q * 2 + 0] = d_bias[q * H_ + hbase + 0];
                bb[q * 2 + 1] = d_bias[q * H_ + hbase + 1];
            }
#pragma unroll
            for (int u = 0; u < 8; u++) {
                const int b = b0g + ty * 8 + u;
                const int tok = __ldcg(&d_tok[b]);
                const float2 cold = *(const float2*)&d_c[b * H_ + hbase];
                const float2 g0 = unp2(acc2[u][0]);
                const float2 g1 = unp2(acc2[u][1]);
                const float2 g2 = unp2(acc2[u][2]);
                const float2 g3 = unp2(acc2[u][3]);
                const float gacc[4][2] = {{g0.x, g0.y}, {g1.x, g1.y}, {g2.x, g2.y}, {g3.x, g3.y}};
                float2 cnew, hnew;
#pragma unroll
                for (int jj = 0; jj < 2; jj++) {
                    const int hcol = hbase + jj;
                    const float gi = gacc[0][jj] + __ldg(&Wih[(size_t)(0 * H_ + hcol) * V_ + tok]) + bb[0 + jj];
                    const float gf = gacc[1][jj] + __ldg(&Wih[(size_t)(1 * H_ + hcol) * V_ + tok]) + bb[2 + jj];
                    const float gg = gacc[2][jj] + __ldg(&Wih[(size_t)(2 * H_ + hcol) * V_ + tok]) + bb[4 + jj];
                    const float go = gacc[3][jj] + __ldg(&Wih[(size_t)(3 * H_ + hcol) * V_ + tok]) + bb[6 + jj];
                    const float co = (jj == 0) ? cold.x : cold.y;
                    const float cn = sigm(gf) * co + sigm(gi) * tanhf(gg);
                    const float hn = sigm(go) * tanhf(cn);
                    if (jj == 0) { cnew.x = cn; hnew.x = hn; }
                    else         { cnew.y = cn; hnew.y = hn; }
                }
                *(float2*)&d_c[b * H_ + hbase]  = cnew;
                *(float2*)&hout[b * H_ + hbase] = hnew;
            }
            stage_barrier();
        }
        stage_barrier();   // final stage (head step 63 runs alone)

    } else {
        // ==================== HEAD ROLE ====================
        float* sbuf = (float*)smem;                          // 8x1024 (h, then z2)
        float (*z1s)[104] = (float (*)[104])(smem + 32768);  // 3328 B
        float* lse_s = (float*)(smem + 32768 + 3328);        // 32 B

        const int hid = blk - NGATES;
        const int b0h = hid * 8;
        const int w = tid >> 5, lane = tid & 31;

        stage_barrier();   // stage 0: gates step 0 runs alone

        for (int t = 0; t < T_; t++) {
            const float* __restrict__ hbuf = d_hbuf[(t + 1) & 1];

            // load 8x512 h rows (coalesced, L2)
            {
                float4* sb4 = (float4*)sbuf;
                const float4* hb4 = (const float4*)(hbuf + (size_t)b0h * H_);
                for (int i = tid; i < 8 * H_ / 4; i += 256) sb4[i] = __ldcg(hb4 + i);
            }
            __syncthreads();

            // z1: warp per output column g, 8 batch accumulators
            for (int g = w; g < GEN_; g += 8) {
                float a[8];
#pragma unroll
                for (int bi = 0; bi < 8; bi++) a[bi] = 0.f;
                const float4* wp = (const float4*)(W1 + (size_t)g * H_);
#pragma unroll
                for (int p = 0; p < 4; p++) {
                    const float4 wv = wp[p * 32 + lane];
#pragma unroll
                    for (int bi = 0; bi < 8; bi++) {
                        const float4 hv = *(const float4*)&sbuf[bi * H_ + (p * 32 + lane) * 4];
                        a[bi] += wv.x * hv.x + wv.y * hv.y + wv.z * hv.z + wv.w * hv.w;
                    }
                }
#pragma unroll
                for (int bi = 0; bi < 8; bi++) {
#pragma unroll
                    for (int off = 16; off; off >>= 1)
                        a[bi] += __shfl_down_sync(0xffffffffu, a[bi], off);
                }
                if (lane == 0) {
                    const float bv = b1[g];
#pragma unroll
                    for (int bi = 0; bi < 8; bi++)
                        z1s[bi][g] = fmaxf(a[bi] + bv, 0.f);
                }
            }
            if (tid < 32) z1s[tid >> 2][100 + (tid & 3)] = 0.f;   // zero pad tail
            __syncthreads();   // h dead; sbuf becomes z2

            // z2: warp-cooperative, coalesced W2 row loads (lanes 0..24)
            float (*z2s)[1024] = (float (*)[1024])sbuf;
            for (int v = w; v < V_; v += 8) {
                float4 wv = make_float4(0.f, 0.f, 0.f, 0.f);
                if (lane < 25) wv = *(const float4*)(W2 + (size_t)v * GEN_ + lane * 4);
                float part[8];
#pragma unroll
                for (int bi = 0; bi < 8; bi++) {
                    float4 z = make_float4(0.f, 0.f, 0.f, 0.f);
                    if (lane < 25) z = *(const float4*)&z1s[bi][lane * 4];
                    part[bi] = wv.x * z.x + wv.y * z.y + wv.z * z.z + wv.w * z.w;
                }
#pragma unroll
                for (int bi = 0; bi < 8; bi++) {
#pragma unroll
                    for (int off = 16; off; off >>= 1)
                        part[bi] += __shfl_down_sync(0xffffffffu, part[bi], off);
                }
                if (lane == 0) {
                    const float bv = b2[v];
#pragma unroll
                    for (int bi = 0; bi < 8; bi++) z2s[bi][v] = part[bi] + bv;
                }
            }
            __syncthreads();

            // argmax + LSE; publish tok ASAP
            {
                float m = -3.0e38f; int mi = 0;
                for (int v = lane; v < V_; v += 32) {
                    const float x = z2s[w][v];
                    if (x > m) { m = x; mi = v; }
                }
#pragma unroll
                for (int off = 16; off; off >>= 1) {
                    const float om  = __shfl_down_sync(0xffffffffu, m, off);
                    const int   omi = __shfl_down_sync(0xffffffffu, mi, off);
                    if (om > m || (om == m && omi < mi)) { m = om; mi = omi; }
                }
                m  = __shfl_sync(0xffffffffu, m, 0);
                mi = __shfl_sync(0xffffffffu, mi, 0);

                float s = 0.f;
                for (int v = lane; v < V_; v += 32) s += expf(z2s[w][v] - m);
#pragma unroll
                for (int off = 16; off; off >>= 1) s += __shfl_down_sync(0xffffffffu, s, off);

                if (lane == 0) {
                    lse_s[w] = m + logf(s);
                    d_tok[b0h + w] = mi;
                }
            }
            __syncthreads();
            __threadfence();
            if (tid == 0) {
                if (atomicAdd(&d_tok_cnt, 1u) == NHEAD - 1) {
                    d_tok_cnt = 0;
                    __threadfence();
                    *((volatile unsigned*)&d_tok_gen) = (unsigned)(t + 1);
                }
            }

            // output writes (overlap with gates epilogue/next stage prep)
            float* orow = out + (size_t)t * B_ * V_ + (size_t)b0h * V_;
            for (int i = tid; i < 8 * V_ / 4; i += 256) {
                const int bi = i >> 8;
                float4 v4 = *(const float4*)&z2s[bi][(i & 255) * 4];
                const float l = lse_s[bi];
                v4.x -= l; v4.y -= l; v4.z -= l; v4.w -= l;
                *(float4*)&orow[i * 4] = v4;
            }
            stage_barrier();
        }
    }
}

// ---------------------------------------------------------------------------
// kernel_launch: 2 graph nodes (init + pipelined persistent loop)
// ---------------------------------------------------------------------------
extern "C" void kernel_launch(void* const* d_in, const int* in_sizes, int n_in,
                              void* d_out, int out_size)
{
    const float* input   = (const float*)d_in[0];
    const float* onehots = (const float*)d_in[1];
    const float* Wh   = (const float*)d_in[4];
    const float* bh   = (const float*)d_in[5];
    const float* Wc   = (const float*)d_in[6];
    const float* bc   = (const float*)d_in[7];
    const float* W_ih = (const float*)d_in[8];
    const float* W_hh = (const float*)d_in[9];
    const float* b_ih = (const float*)d_in[10];
    const float* b_hh = (const float*)d_in[11];
    const float* W1   = (const float*)d_in[12];
    const float* b1   = (const float*)d_in[13];
    const float* W2   = (const float*)d_in[14];
    const float* b2   = (const float*)d_in[15];
    float* out = (float*)d_out;

    init_kernel<<<B_, 256>>>(input, onehots, Wh, bh, Wc, bc, b_ih, b_hh);
    lstm_pipeline_kernel<<<NTOT, 256>>>(W_hh, W_ih, W1, b1, W2, b2, out);
}

// round 9
// speedup vs baseline: 2.3057x; 2.0019x over previous
#include <cuda_runtime.h>
#include <math.h>

// Problem constants
#define B_   1024
#define T_   64
#define H_   512
#define V_   1024
#define GEN_ 100
#define H4_  2048
#define NGATES 128
#define NHEAD  128
#define NTOT   256

typedef unsigned long long ull;

// Persistent state (device globals — no allocation allowed)
__device__ float d_hbuf[2][B_ * H_];   // ping-pong hidden state
__device__ float d_c[B_ * H_];         // cell state
__device__ float d_bias[H4_];          // b_ih + b_hh
__device__ float d_W2T[GEN_ * V_];     // W2 transposed: [k][v]
__device__ int   d_tok[B_];            // current token per batch row
__device__ unsigned d_bar_count;       // 256-block stage barrier
__device__ unsigned d_bar_gen;
__device__ unsigned d_tok_cnt;         // head-completion counter
__device__ unsigned d_tok_gen;         // number of completed head steps

__device__ __forceinline__ float sigm(float x) { return 1.0f / (1.0f + expf(-x)); }

__device__ __forceinline__ ull dup2(float x) {
    ull r; asm("mov.b64 %0, {%1, %1};" : "=l"(r) : "f"(x)); return r;
}
__device__ __forceinline__ ull pack2(float a, float b) {
    ull r; asm("mov.b64 %0, {%1, %2};" : "=l"(r) : "f"(a), "f"(b)); return r;
}
__device__ __forceinline__ void ffma2(ull& d, ull a, ull b) {
    asm("fma.rn.f32x2 %0, %1, %2, %0;" : "+l"(d) : "l"(a), "l"(b));
}
__device__ __forceinline__ float2 unp2(ull v) {
    float2 f; asm("mov.b64 {%0, %1}, %2;" : "=f"(f.x), "=f"(f.y) : "l"(v)); return f;
}

// Stage barrier across all NTOT blocks (all co-resident: 256 <= 2*148 CTAs).
__device__ __forceinline__ void stage_barrier() {
    __threadfence();
    __syncthreads();
    if (threadIdx.x == 0) {
        const unsigned gen = *((volatile unsigned*)&d_bar_gen);
        if (atomicAdd(&d_bar_count, 1u) == NTOT - 1) {
            d_bar_count = 0;
            __threadfence();
            *((volatile unsigned*)&d_bar_gen) = gen + 1;
        } else {
            while (*((volatile unsigned*)&d_bar_gen) == gen) { __nanosleep(32); }
        }
    }
    __syncthreads();
}

// ---------------------------------------------------------------------------
// init: h0/c0 ; bias ; tok0 ; reset counters
// ---------------------------------------------------------------------------
__global__ void init_kernel(const float* __restrict__ input,
                            const float* __restrict__ onehots,
                            const float* __restrict__ Wh, const float* __restrict__ bh,
                            const float* __restrict__ Wc, const float* __restrict__ bc,
                            const float* __restrict__ b_ih, const float* __restrict__ b_hh)
{
    const int b = blockIdx.x;
    const int tid = threadIdx.x;
    const float xv = input[b];

    if (b == 0 && tid == 0) {
        d_bar_count = 0; d_bar_gen = 0; d_tok_cnt = 0; d_tok_gen = 0;
    }
    for (int i = tid; i < H_; i += 256) {
        d_hbuf[0][b * H_ + i] = xv * Wh[i] + bh[i];
        d_c[b * H_ + i]       = xv * Wc[i] + bc[i];
    }
    if (b < H4_ / 256) {
        const int j = b * 256 + tid;
        d_bias[j] = b_ih[j] + b_hh[j];
    }
    const float* oh = onehots + (size_t)b * T_ * V_;
    for (int v = tid; v < V_; v += 256)
        if (oh[v] > 0.5f) d_tok[b] = v;
}

// W2T[k][v] = W2[v][k]   (100 blocks x 256 threads, writes coalesced per k)
__global__ void transpose_w2_kernel(const float* __restrict__ W2)
{
    const int k = blockIdx.x;
    for (int v = threadIdx.x; v < V_; v += 256)
        d_W2T[k * V_ + v] = __ldg(&W2[(size_t)v * GEN_ + k]);
}

// ---------------------------------------------------------------------------
// Pipelined persistent kernel.
// Blocks 0..127: gates role.  Blocks 128..255: head role.  2 CTAs/SM.
// Stage s: gates step s  ||  head step s-1.
// Head publishes tok_t mid-stage (right after argmax), before its 32KB
// output stores, so the gates epilogue wait is short.
// ---------------------------------------------------------------------------
__global__ void __launch_bounds__(256, 2)
lstm_pipeline_kernel(const float* __restrict__ Whh,
                     const float* __restrict__ Wih,
                     const float* __restrict__ W1, const float* __restrict__ b1,
                     const float* __restrict__ b2,
                     float* __restrict__ out)
{
    __shared__ __align__(16) char smem[39552];
    const int tid = threadIdx.x;
    const int blk = blockIdx.x;

    if (blk < NGATES) {
        // ==================== GATES ROLE ====================
        float (*hsm)[132] = (float (*)[132])smem;            // 16x132
        float (*wsm)[132] = (float (*)[132])(smem + 8448);   // 16x132

        const int gbx = blk & 7;            // b-tile (128 rows)
        const int gby = blk >> 3;           // h-tile (32 cols)
        const int b0g = gbx * 128;
        const int h0g = gby * 32;
        const int tx = tid & 15;            // 2-h-column group
        const int ty = tid >> 4;            // 8-b-row group

        const int r0 = tid >> 2,          kq0 = (tid & 3) * 4;
        const int r1 = (tid + 256) >> 2,  kq1 = ((tid + 256) & 3) * 4;
        const int wrow0 = (r0 >> 5) * H_ + h0g + (r0 & 31);
        const int wrow1 = (r1 >> 5) * H_ + h0g + (r1 & 31);
        const float* wb0 = Whh + (size_t)wrow0 * H_ + kq0;
        const float* wb1 = Whh + (size_t)wrow1 * H_ + kq1;

        for (int t = 0; t < T_; t++) {
            const int par = t & 1;
            const float* __restrict__ hin  = d_hbuf[par];
            float* __restrict__       hout = d_hbuf[par ^ 1];
            const float4* hb0 = (const float4*)(hin + (size_t)(b0g + r0) * H_ + kq0);
            const float4* hb1 = (const float4*)(hin + (size_t)(b0g + r1) * H_ + kq1);

            ull acc2[8][4];
#pragma unroll
            for (int u = 0; u < 8; u++)
#pragma unroll
                for (int j = 0; j < 4; j++) acc2[u][j] = 0ull;

            float4 ph0 = __ldcg(hb0);
            float4 ph1 = __ldcg(hb1);
            float4 pw0 = *(const float4*)(wb0);
            float4 pw1 = *(const float4*)(wb1);

            for (int k0 = 0; k0 < H_; k0 += 16) {
                hsm[kq0 + 0][r0] = ph0.x; hsm[kq0 + 1][r0] = ph0.y;
                hsm[kq0 + 2][r0] = ph0.z; hsm[kq0 + 3][r0] = ph0.w;
                hsm[kq1 + 0][r1] = ph1.x; hsm[kq1 + 1][r1] = ph1.y;
                hsm[kq1 + 2][r1] = ph1.z; hsm[kq1 + 3][r1] = ph1.w;
                wsm[kq0 + 0][r0] = pw0.x; wsm[kq0 + 1][r0] = pw0.y;
                wsm[kq0 + 2][r0] = pw0.z; wsm[kq0 + 3][r0] = pw0.w;
                wsm[kq1 + 0][r1] = pw1.x; wsm[kq1 + 1][r1] = pw1.y;
                wsm[kq1 + 2][r1] = pw1.z; wsm[kq1 + 3][r1] = pw1.w;
                __syncthreads();

                if (k0 + 16 < H_) {
                    ph0 = __ldcg(hb0 + (k0 + 16) / 4);
                    ph1 = __ldcg(hb1 + (k0 + 16) / 4);
                    pw0 = *(const float4*)(wb0 + k0 + 16);
                    pw1 = *(const float4*)(wb1 + k0 + 16);
                }

#pragma unroll
                for (int kk = 0; kk < 16; kk++) {
                    const float4 a0 = *(const float4*)&hsm[kk][ty * 8];
                    const float4 a1 = *(const float4*)&hsm[kk][ty * 8 + 4];
                    const ull w0 = *(const ull*)&wsm[kk][      tx * 2];
                    const ull w1 = *(const ull*)&wsm[kk][32  + tx * 2];
                    const ull w2 = *(const ull*)&wsm[kk][64  + tx * 2];
                    const ull w3 = *(const ull*)&wsm[kk][96  + tx * 2];
                    const float hv[8] = {a0.x, a0.y, a0.z, a0.w, a1.x, a1.y, a1.z, a1.w};
#pragma unroll
                    for (int u = 0; u < 8; u++) {
                        const ull h2 = dup2(hv[u]);
                        ffma2(acc2[u][0], h2, w0);
                        ffma2(acc2[u][1], h2, w1);
                        ffma2(acc2[u][2], h2, w2);
                        ffma2(acc2[u][3], h2, w3);
                    }
                }
                __syncthreads();
            }

            // wait for tok_{t-1} (published mid-stage by head step t-1)
            if (t > 0) {
                if (tid == 0) {
                    while (*((volatile unsigned*)&d_tok_gen) < (unsigned)t) { __nanosleep(32); }
                }
                __syncthreads();
            }

            // fused LSTM cell epilogue
            const int hbase = h0g + tx * 2;
            float bb[8];
#pragma unroll
            for (int q = 0; q < 4; q++) {
                bb[q * 2 + 0] = d_bias[q * H_ + hbase + 0];
                bb[q * 2 + 1] = d_bias[q * H_ + hbase + 1];
            }
#pragma unroll
            for (int u = 0; u < 8; u++) {
                const int b = b0g + ty * 8 + u;
                const int tok = __ldcg(&d_tok[b]);
                const float2 cold = *(const float2*)&d_c[b * H_ + hbase];
                const float2 g0 = unp2(acc2[u][0]);
                const float2 g1 = unp2(acc2[u][1]);
                const float2 g2 = unp2(acc2[u][2]);
                const float2 g3 = unp2(acc2[u][3]);
                const float gacc[4][2] = {{g0.x, g0.y}, {g1.x, g1.y}, {g2.x, g2.y}, {g3.x, g3.y}};
                float2 cnew, hnew;
#pragma unroll
                for (int jj = 0; jj < 2; jj++) {
                    const int hcol = hbase + jj;
                    const float gi = gacc[0][jj] + __ldg(&Wih[(size_t)(0 * H_ + hcol) * V_ + tok]) + bb[0 + jj];
                    const float gf = gacc[1][jj] + __ldg(&Wih[(size_t)(1 * H_ + hcol) * V_ + tok]) + bb[2 + jj];
                    const float gg = gacc[2][jj] + __ldg(&Wih[(size_t)(2 * H_ + hcol) * V_ + tok]) + bb[4 + jj];
                    const float go = gacc[3][jj] + __ldg(&Wih[(size_t)(3 * H_ + hcol) * V_ + tok]) + bb[6 + jj];
                    const float co = (jj == 0) ? cold.x : cold.y;
                    const float cn = sigm(gf) * co + sigm(gi) * tanhf(gg);
                    const float hn = sigm(go) * tanhf(cn);
                    if (jj == 0) { cnew.x = cn; hnew.x = hn; }
                    else         { cnew.y = cn; hnew.y = hn; }
                }
                *(float2*)&d_c[b * H_ + hbase]  = cnew;
                *(float2*)&hout[b * H_ + hbase] = hnew;
            }
            stage_barrier();
        }
        stage_barrier();   // final stage (head step 63 runs alone)

    } else {
        // ==================== HEAD ROLE ====================
        float* sbuf = (float*)smem;                            // 8x1024 (h, then z2)
        float2 (*z1d)[104] = (float2 (*)[104])(smem + 32768);  // duplicated z1 pairs, 6656 B
        float* lse_s = (float*)(smem + 32768 + 6656);          // 32 B

        const int hid = blk - NGATES;
        const int b0h = hid * 8;
        const int w = tid >> 5, lane = tid & 31;

        stage_barrier();   // stage 0: gates step 0 runs alone

        for (int t = 0; t < T_; t++) {
            const float* __restrict__ hbuf = d_hbuf[(t + 1) & 1];

            // load 8x512 h rows (coalesced, L2)
            {
                float4* sb4 = (float4*)sbuf;
                const float4* hb4 = (const float4*)(hbuf + (size_t)b0h * H_);
                for (int i = tid; i < 8 * H_ / 4; i += 256) sb4[i] = __ldcg(hb4 + i);
            }
            __syncthreads();

            // z1: warp per output column g, 8 batch accumulators; store duplicated pair
            for (int g = w; g < GEN_; g += 8) {
                float a[8];
#pragma unroll
                for (int bi = 0; bi < 8; bi++) a[bi] = 0.f;
                const float4* wp = (const float4*)(W1 + (size_t)g * H_);
#pragma unroll
                for (int p = 0; p < 4; p++) {
                    const float4 wv = __ldcg(wp + p * 32 + lane);
#pragma unroll
                    for (int bi = 0; bi < 8; bi++) {
                        const float4 hv = *(const float4*)&sbuf[bi * H_ + (p * 32 + lane) * 4];
                        a[bi] += wv.x * hv.x + wv.y * hv.y + wv.z * hv.z + wv.w * hv.w;
                    }
                }
#pragma unroll
                for (int bi = 0; bi < 8; bi++) {
#pragma unroll
                    for (int off = 16; off; off >>= 1)
                        a[bi] += __shfl_down_sync(0xffffffffu, a[bi], off);
                }
                if (lane == 0) {
                    const float bv = b1[g];
#pragma unroll
                    for (int bi = 0; bi < 8; bi++) {
                        const float z = fmaxf(a[bi] + bv, 0.f);
                        z1d[bi][g] = make_float2(z, z);
                    }
                }
            }
            __syncthreads();   // h dead; sbuf becomes z2

            // z2: thread owns 4 consecutive v; coalesced W2T rows; FFMA2 accs
            float (*z2s)[1024] = (float (*)[1024])sbuf;
            {
                const int v0 = tid * 4;
                ull acc[8][2];
                {
                    const float4 bv = *(const float4*)(b2 + v0);
                    const ull bl = pack2(bv.x, bv.y), bh2 = pack2(bv.z, bv.w);
#pragma unroll
                    for (int bi = 0; bi < 8; bi++) { acc[bi][0] = bl; acc[bi][1] = bh2; }
                }
#pragma unroll 5
                for (int k = 0; k < GEN_; k++) {
                    const float4 wv = __ldcg((const float4*)(d_W2T + k * V_ + v0));
                    const ull wl = pack2(wv.x, wv.y), wh = pack2(wv.z, wv.w);
#pragma unroll
                    for (int bi = 0; bi < 8; bi++) {
                        const ull z = *(const ull*)&z1d[bi][k];
                        ffma2(acc[bi][0], z, wl);
                        ffma2(acc[bi][1], z, wh);
                    }
                }
#pragma unroll
                for (int bi = 0; bi < 8; bi++) {
                    const float2 lo = unp2(acc[bi][0]);
                    const float2 hi = unp2(acc[bi][1]);
                    *(float4*)&z2s[bi][v0] = make_float4(lo.x, lo.y, hi.x, hi.y);
                }
            }
            __syncthreads();

            // argmax + LSE; publish tok ASAP
            {
                float m = -3.0e38f; int mi = 0;
                for (int v = lane; v < V_; v += 32) {
                    const float x = z2s[w][v];
                    if (x > m) { m = x; mi = v; }
                }
#pragma unroll
                for (int off = 16; off; off >>= 1) {
                    const float om  = __shfl_down_sync(0xffffffffu, m, off);
                    const int   omi = __shfl_down_sync(0xffffffffu, mi, off);
                    if (om > m || (om == m && omi < mi)) { m = om; mi = omi; }
                }
                m  = __shfl_sync(0xffffffffu, m, 0);
                mi = __shfl_sync(0xffffffffu, mi, 0);

                float s = 0.f;
                for (int v = lane; v < V_; v += 32) s += expf(z2s[w][v] - m);
#pragma unroll
                for (int off = 16; off; off >>= 1) s += __shfl_down_sync(0xffffffffu, s, off);

                if (lane == 0) {
                    lse_s[w] = m + logf(s);
                    d_tok[b0h + w] = mi;
                }
            }
            __syncthreads();
            __threadfence();
            if (tid == 0) {
                if (atomicAdd(&d_tok_cnt, 1u) == NHEAD - 1) {
                    d_tok_cnt = 0;
                    __threadfence();
                    *((volatile unsigned*)&d_tok_gen) = (unsigned)(t + 1);
                }
            }

            // output writes (overlap with gates' remaining work)
            float* orow = out + (size_t)t * B_ * V_ + (size_t)b0h * V_;
            for (int i = tid; i < 8 * V_ / 4; i += 256) {
                const int bi = i >> 8;
                float4 v4 = *(const float4*)&z2s[bi][(i & 255) * 4];
                const float l = lse_s[bi];
                v4.x -= l; v4.y -= l; v4.z -= l; v4.w -= l;
                *(float4*)&orow[i * 4] = v4;
            }
            stage_barrier();
        }
    }
}

// ---------------------------------------------------------------------------
// kernel_launch: 3 graph nodes (init + W2 transpose + persistent loop)
// ---------------------------------------------------------------------------
extern "C" void kernel_launch(void* const* d_in, const int* in_sizes, int n_in,
                              void* d_out, int out_size)
{
    const float* input   = (const float*)d_in[0];
    const float* onehots = (const float*)d_in[1];
    const float* Wh   = (const float*)d_in[4];
    const float* bh   = (const float*)d_in[5];
    const float* Wc   = (const float*)d_in[6];
    const float* bc   = (const float*)d_in[7];
    const float* W_ih = (const float*)d_in[8];
    const float* W_hh = (const float*)d_in[9];
    const float* b_ih = (const float*)d_in[10];
    const float* b_hh = (const float*)d_in[11];
    const float* W1   = (const float*)d_in[12];
    const float* b1   = (const float*)d_in[13];
    const float* W2   = (const float*)d_in[14];
    const float* b2   = (const float*)d_in[15];
    float* out = (float*)d_out;

    init_kernel<<<B_, 256>>>(input, onehots, Wh, bh, Wc, bc, b_ih, b_hh);
    transpose_w2_kernel<<<GEN_, 256>>>(W2);
    lstm_pipeline_kernel<<<NTOT, 256>>>(W_hh, W_ih, W1, b1, b2, out);
}

// round 10
// speedup vs baseline: 2.4054x; 1.0432x over previous
#include <cuda_runtime.h>
#include <math.h>

// Problem constants
#define B_   1024
#define T_   64
#define H_   512
#define V_   1024
#define GEN_ 100
#define H4_  2048
#define NGATES 128
#define NHEAD  128
#define NTOT   256

typedef unsigned long long ull;

// Persistent state (device globals — no allocation allowed)
__device__ float d_hbuf[2][B_ * H_];   // ping-pong hidden state
__device__ float d_c[B_ * H_];         // cell state
__device__ float d_bias[H4_];          // b_ih + b_hh
__device__ float d_W2T[GEN_ * V_];     // W2 transposed: [k][v]
__device__ float d_WihT[V_ * H4_];     // W_ih transposed: [tok][4H]
__device__ int   d_tok[B_];            // current token per batch row
__device__ unsigned d_bar_count;       // 256-block stage barrier
__device__ unsigned d_bar_gen;
__device__ unsigned d_tok_cnt;         // head-completion counter
__device__ unsigned d_tok_gen;         // number of completed head steps

__device__ __forceinline__ float sigm(float x) { return 1.0f / (1.0f + expf(-x)); }

__device__ __forceinline__ ull dup2(float x) {
    ull r; asm("mov.b64 %0, {%1, %1};" : "=l"(r) : "f"(x)); return r;
}
__device__ __forceinline__ ull pack2(float a, float b) {
    ull r; asm("mov.b64 %0, {%1, %2};" : "=l"(r) : "f"(a), "f"(b)); return r;
}
__device__ __forceinline__ void ffma2(ull& d, ull a, ull b) {
    asm("fma.rn.f32x2 %0, %1, %2, %0;" : "+l"(d) : "l"(a), "l"(b));
}
__device__ __forceinline__ float2 unp2(ull v) {
    float2 f; asm("mov.b64 {%0, %1}, %2;" : "=f"(f.x), "=f"(f.y) : "l"(v)); return f;
}

// Stage barrier across all NTOT blocks (all co-resident: 256 <= 2*148 CTAs).
__device__ __forceinline__ void stage_barrier() {
    __threadfence();
    __syncthreads();
    if (threadIdx.x == 0) {
        const unsigned gen = *((volatile unsigned*)&d_bar_gen);
        if (atomicAdd(&d_bar_count, 1u) == NTOT - 1) {
            d_bar_count = 0;
            __threadfence();
            *((volatile unsigned*)&d_bar_gen) = gen + 1;
        } else {
            while (*((volatile unsigned*)&d_bar_gen) == gen) { __nanosleep(32); }
        }
    }
    __syncthreads();
}

// ---------------------------------------------------------------------------
// init: h0/c0 ; bias ; tok0 ; reset counters
// ---------------------------------------------------------------------------
__global__ void init_kernel(const float* __restrict__ input,
                            const float* __restrict__ onehots,
                            const float* __restrict__ Wh, const float* __restrict__ bh,
                            const float* __restrict__ Wc, const float* __restrict__ bc,
                            const float* __restrict__ b_ih, const float* __restrict__ b_hh)
{
    const int b = blockIdx.x;
    const int tid = threadIdx.x;
    const float xv = input[b];

    if (b == 0 && tid == 0) {
        d_bar_count = 0; d_bar_gen = 0; d_tok_cnt = 0; d_tok_gen = 0;
    }
    for (int i = tid; i < H_; i += 256) {
        d_hbuf[0][b * H_ + i] = xv * Wh[i] + bh[i];
        d_c[b * H_ + i]       = xv * Wc[i] + bc[i];
    }
    if (b < H4_ / 256) {
        const int j = b * 256 + tid;
        d_bias[j] = b_ih[j] + b_hh[j];
    }
    const float* oh = onehots + (size_t)b * T_ * V_;
    for (int v = tid; v < V_; v += 256)
        if (oh[v] > 0.5f) d_tok[b] = v;
}

// W2T[k][v] = W2[v][k]   (100 blocks x 256 threads, writes coalesced per k)
__global__ void transpose_w2_kernel(const float* __restrict__ W2)
{
    const int k = blockIdx.x;
    for (int v = threadIdx.x; v < V_; v += 256)
        d_W2T[k * V_ + v] = __ldg(&W2[(size_t)v * GEN_ + k]);
}

// WihT[v][j] = Wih[j][v], tiled transpose. grid (64, 32) x 256 threads.
__global__ void transpose_wih_kernel(const float* __restrict__ Wih)
{
    __shared__ float tile[32][33];
    const int j0 = blockIdx.x * 32;     // row block in Wih (4H dim)
    const int v0 = blockIdx.y * 32;     // col block in Wih (V dim)
    const int tx = threadIdx.x & 31;
    const int ty = threadIdx.x >> 5;    // 8 rows at a time

    for (int r = ty; r < 32; r += 8)
        tile[r][tx] = Wih[(size_t)(j0 + r) * V_ + v0 + tx];
    __syncthreads();
    for (int r = ty; r < 32; r += 8)
        d_WihT[(size_t)(v0 + r) * H4_ + j0 + tx] = tile[tx][r];
}

// ---------------------------------------------------------------------------
// Pipelined persistent kernel.
// Blocks 0..127: gates role.  Blocks 128..255: head role.  2 CTAs/SM.
// Stage s: gates step s  ||  head step s-1.
// ---------------------------------------------------------------------------
__global__ void __launch_bounds__(256, 2)
lstm_pipeline_kernel(const float* __restrict__ Whh,
                     const float* __restrict__ W1, const float* __restrict__ b1,
                     const float* __restrict__ b2,
                     float* __restrict__ out)
{
    __shared__ __align__(16) char smem[39552];
    const int tid = threadIdx.x;
    const int blk = blockIdx.x;

    if (blk < NGATES) {
        // ==================== GATES ROLE ====================
        // double-buffered tiles: hsm[2][16][132], wsm[2][16][132]
        float (*hsmb)[16][132] = (float (*)[16][132])smem;              // 2x8448
        float (*wsmb)[16][132] = (float (*)[16][132])(smem + 16896);    // 2x8448
        int* tok_s = (int*)(smem + 33792);                              // 512 B

        const int gbx = blk & 7;            // b-tile (128 rows)
        const int gby = blk >> 3;           // h-tile (32 cols)
        const int b0g = gbx * 128;
        const int h0g = gby * 32;
        const int tx = tid & 15;            // 2-h-column group
        const int ty = tid >> 4;            // 8-b-row group

        const int r0 = tid >> 2,          kq0 = (tid & 3) * 4;
        const int r1 = (tid + 256) >> 2,  kq1 = ((tid + 256) & 3) * 4;
        const int wrow0 = (r0 >> 5) * H_ + h0g + (r0 & 31);
        const int wrow1 = (r1 >> 5) * H_ + h0g + (r1 & 31);
        const float4* wb0 = (const float4*)(Whh + (size_t)wrow0 * H_ + kq0);
        const float4* wb1 = (const float4*)(Whh + (size_t)wrow1 * H_ + kq1);

        for (int t = 0; t < T_; t++) {
            const int par = t & 1;
            const float* __restrict__ hin  = d_hbuf[par];
            float* __restrict__       hout = d_hbuf[par ^ 1];
            const float4* hb0 = (const float4*)(hin + (size_t)(b0g + r0) * H_ + kq0);
            const float4* hb1 = (const float4*)(hin + (size_t)(b0g + r1) * H_ + kq1);

            ull acc2[8][4];
#pragma unroll
            for (int u = 0; u < 8; u++)
#pragma unroll
                for (int j = 0; j < 4; j++) acc2[u][j] = 0ull;

            // fill buffer 0 (chunk 0)
            {
                const float4 ph0 = __ldcg(hb0);
                const float4 ph1 = __ldcg(hb1);
                const float4 pw0 = __ldcg(wb0);
                const float4 pw1 = __ldcg(wb1);
                hsmb[0][kq0 + 0][r0] = ph0.x; hsmb[0][kq0 + 1][r0] = ph0.y;
                hsmb[0][kq0 + 2][r0] = ph0.z; hsmb[0][kq0 + 3][r0] = ph0.w;
                hsmb[0][kq1 + 0][r1] = ph1.x; hsmb[0][kq1 + 1][r1] = ph1.y;
                hsmb[0][kq1 + 2][r1] = ph1.z; hsmb[0][kq1 + 3][r1] = ph1.w;
                wsmb[0][kq0 + 0][r0] = pw0.x; wsmb[0][kq0 + 1][r0] = pw0.y;
                wsmb[0][kq0 + 2][r0] = pw0.z; wsmb[0][kq0 + 3][r0] = pw0.w;
                wsmb[0][kq1 + 0][r1] = pw1.x; wsmb[0][kq1 + 1][r1] = pw1.y;
                wsmb[0][kq1 + 2][r1] = pw1.z; wsmb[0][kq1 + 3][r1] = pw1.w;
            }
            __syncthreads();

            for (int c = 0; c < 32; c++) {
                const int cur = c & 1;
                float4 nh0, nh1, nw0, nw1;
                const bool hasNext = (c + 1 < 32);
                if (hasNext) {
                    nh0 = __ldcg(hb0 + (c + 1) * 4);
                    nh1 = __ldcg(hb1 + (c + 1) * 4);
                    nw0 = __ldcg(wb0 + (c + 1) * 4);
                    nw1 = __ldcg(wb1 + (c + 1) * 4);
                }

#pragma unroll
                for (int kk = 0; kk < 16; kk++) {
                    const float4 a0 = *(const float4*)&hsmb[cur][kk][ty * 8];
                    const float4 a1 = *(const float4*)&hsmb[cur][kk][ty * 8 + 4];
                    const ull w0 = *(const ull*)&wsmb[cur][kk][      tx * 2];
                    const ull w1 = *(const ull*)&wsmb[cur][kk][32  + tx * 2];
                    const ull w2 = *(const ull*)&wsmb[cur][kk][64  + tx * 2];
                    const ull w3 = *(const ull*)&wsmb[cur][kk][96  + tx * 2];
                    const float hv[8] = {a0.x, a0.y, a0.z, a0.w, a1.x, a1.y, a1.z, a1.w};
#pragma unroll
                    for (int u = 0; u < 8; u++) {
                        const ull h2 = dup2(hv[u]);
                        ffma2(acc2[u][0], h2, w0);
                        ffma2(acc2[u][1], h2, w1);
                        ffma2(acc2[u][2], h2, w2);
                        ffma2(acc2[u][3], h2, w3);
                    }
                }

                if (hasNext) {
                    const int nxt = cur ^ 1;
                    hsmb[nxt][kq0 + 0][r0] = nh0.x; hsmb[nxt][kq0 + 1][r0] = nh0.y;
                    hsmb[nxt][kq0 + 2][r0] = nh0.z; hsmb[nxt][kq0 + 3][r0] = nh0.w;
                    hsmb[nxt][kq1 + 0][r1] = nh1.x; hsmb[nxt][kq1 + 1][r1] = nh1.y;
                    hsmb[nxt][kq1 + 2][r1] = nh1.z; hsmb[nxt][kq1 + 3][r1] = nh1.w;
                    wsmb[nxt][kq0 + 0][r0] = nw0.x; wsmb[nxt][kq0 + 1][r0] = nw0.y;
                    wsmb[nxt][kq0 + 2][r0] = nw0.z; wsmb[nxt][kq0 + 3][r0] = nw0.w;
                    wsmb[nxt][kq1 + 0][r1] = nw1.x; wsmb[nxt][kq1 + 1][r1] = nw1.y;
                    wsmb[nxt][kq1 + 2][r1] = nw1.z; wsmb[nxt][kq1 + 3][r1] = nw1.w;
                }
                __syncthreads();
            }

            // wait for tok_{t-1}, then stage tokens into smem (coalesced)
            if (t > 0 && tid == 0) {
                while (*((volatile unsigned*)&d_tok_gen) < (unsigned)t) { __nanosleep(32); }
            }
            __syncthreads();
            if (tid < 128) tok_s[tid] = __ldcg(&d_tok[b0g + tid]);
            __syncthreads();

            // fused LSTM cell epilogue (coalesced WihT gather)
            const int hbase = h0g + tx * 2;
            float bb[8];
#pragma unroll
            for (int q = 0; q < 4; q++) {
                bb[q * 2 + 0] = d_bias[q * H_ + hbase + 0];
                bb[q * 2 + 1] = d_bias[q * H_ + hbase + 1];
            }
#pragma unroll
            for (int u = 0; u < 8; u++) {
                const int b = b0g + ty * 8 + u;
                const int tok = tok_s[ty * 8 + u];
                const float* WT = d_WihT + (size_t)tok * H4_;
                const float2 wi0 = __ldcg((const float2*)&WT[0 * H_ + hbase]);
                const float2 wi1 = __ldcg((const float2*)&WT[1 * H_ + hbase]);
                const float2 wi2 = __ldcg((const float2*)&WT[2 * H_ + hbase]);
                const float2 wi3 = __ldcg((const float2*)&WT[3 * H_ + hbase]);
                const float2 cold = *(const float2*)&d_c[b * H_ + hbase];
                const float2 g0 = unp2(acc2[u][0]);
                const float2 g1 = unp2(acc2[u][1]);
                const float2 g2 = unp2(acc2[u][2]);
                const float2 g3 = unp2(acc2[u][3]);
                float2 cnew, hnew;
                {
                    const float gi = g0.x + wi0.x + bb[0];
                    const float gf = g1.x + wi1.x + bb[2];
                    const float gg = g2.x + wi2.x + bb[4];
                    const float go = g3.x + wi3.x + bb[6];
                    const float cn = sigm(gf) * cold.x + sigm(gi) * tanhf(gg);
                    cnew.x = cn; hnew.x = sigm(go) * tanhf(cn);
                }
                {
                    const float gi = g0.y + wi0.y + bb[1];
                    const float gf = g1.y + wi1.y + bb[3];
                    const float gg = g2.y + wi2.y + bb[5];
                    const float go = g3.y + wi3.y + bb[7];
                    const float cn = sigm(gf) * cold.y + sigm(gi) * tanhf(gg);
                    cnew.y = cn; hnew.y = sigm(go) * tanhf(cn);
                }
                *(float2*)&d_c[b * H_ + hbase]  = cnew;
                *(float2*)&hout[b * H_ + hbase] = hnew;
            }
            stage_barrier();
        }
        stage_barrier();   // final stage (head step 63 runs alone)

    } else {
        // ==================== HEAD ROLE ====================
        float* sbuf = (float*)smem;                            // 8x1024 (h, then z2)
        float2 (*z1d)[104] = (float2 (*)[104])(smem + 32768);  // duplicated z1 pairs, 6656 B
        float* lse_s = (float*)(smem + 32768 + 6656);          // 32 B

        const int hid = blk - NGATES;
        const int b0h = hid * 8;
        const int w = tid >> 5, lane = tid & 31;

        stage_barrier();   // stage 0: gates step 0 runs alone

        for (int t = 0; t < T_; t++) {
            const float* __restrict__ hbuf = d_hbuf[(t + 1) & 1];

            // load 8x512 h rows (coalesced, L2)
            {
                float4* sb4 = (float4*)sbuf;
                const float4* hb4 = (const float4*)(hbuf + (size_t)b0h * H_);
                for (int i = tid; i < 8 * H_ / 4; i += 256) sb4[i] = __ldcg(hb4 + i);
            }
            __syncthreads();

            // z1: warp per output column g, 8 batch accumulators; store duplicated pair
            for (int g = w; g < GEN_; g += 8) {
                float a[8];
#pragma unroll
                for (int bi = 0; bi < 8; bi++) a[bi] = 0.f;
                const float4* wp = (const float4*)(W1 + (size_t)g * H_);
#pragma unroll
                for (int p = 0; p < 4; p++) {
                    const float4 wv = __ldg(wp + p * 32 + lane);
#pragma unroll
                    for (int bi = 0; bi < 8; bi++) {
                        const float4 hv = *(const float4*)&sbuf[bi * H_ + (p * 32 + lane) * 4];
                        a[bi] += wv.x * hv.x + wv.y * hv.y + wv.z * hv.z + wv.w * hv.w;
                    }
                }
#pragma unroll
                for (int bi = 0; bi < 8; bi++) {
#pragma unroll
                    for (int off = 16; off; off >>= 1)
                        a[bi] += __shfl_down_sync(0xffffffffu, a[bi], off);
                }
                if (lane == 0) {
                    const float bv = b1[g];
#pragma unroll
                    for (int bi = 0; bi < 8; bi++) {
                        const float z = fmaxf(a[bi] + bv, 0.f);
                        z1d[bi][g] = make_float2(z, z);
                    }
                }
            }
            __syncthreads();   // h dead; sbuf becomes z2

            // z2: thread owns 4 consecutive v; coalesced W2T rows; FFMA2 accs
            float (*z2s)[1024] = (float (*)[1024])sbuf;
            {
                const int v0 = tid * 4;
                ull acc[8][2];
                {
                    const float4 bv = *(const float4*)(b2 + v0);
                    const ull bl = pack2(bv.x, bv.y), bh2 = pack2(bv.z, bv.w);
#pragma unroll
                    for (int bi = 0; bi < 8; bi++) { acc[bi][0] = bl; acc[bi][1] = bh2; }
                }
#pragma unroll 5
                for (int k = 0; k < GEN_; k++) {
                    const float4 wv = __ldcg((const float4*)(d_W2T + k * V_ + v0));
                    const ull wl = pack2(wv.x, wv.y), wh = pack2(wv.z, wv.w);
#pragma unroll
                    for (int bi = 0; bi < 8; bi++) {
                        const ull z = *(const ull*)&z1d[bi][k];
                        ffma2(acc[bi][0], z, wl);
                        ffma2(acc[bi][1], z, wh);
                    }
                }
#pragma unroll
                for (int bi = 0; bi < 8; bi++) {
                    const float2 lo = unp2(acc[bi][0]);
                    const float2 hi = unp2(acc[bi][1]);
                    *(float4*)&z2s[bi][v0] = make_float4(lo.x, lo.y, hi.x, hi.y);
                }
            }
            __syncthreads();

            // argmax + LSE; publish tok ASAP
            {
                float m = -3.0e38f; int mi = 0;
                for (int v = lane; v < V_; v += 32) {
                    const float x = z2s[w][v];
                    if (x > m) { m = x; mi = v; }
                }
#pragma unroll
                for (int off = 16; off; off >>= 1) {
                    const float om  = __shfl_down_sync(0xffffffffu, m, off);
                    const int   omi = __shfl_down_sync(0xffffffffu, mi, off);
                    if (om > m || (om == m && omi < mi)) { m = om; mi = omi; }
                }
                m  = __shfl_sync(0xffffffffu, m, 0);
                mi = __shfl_sync(0xffffffffu, mi, 0);

                float s = 0.f;
                for (int v = lane; v < V_; v += 32) s += expf(z2s[w][v] - m);
#pragma unroll
                for (int off = 16; off; off >>= 1) s += __shfl_down_sync(0xffffffffu, s, off);

                if (lane == 0) {
                    lse_s[w] = m + logf(s);
                    d_tok[b0h + w] = mi;
                }
            }
            __syncthreads();
            __threadfence();
            if (tid == 0) {
                if (atomicAdd(&d_tok_cnt, 1u) == NHEAD - 1) {
                    d_tok_cnt = 0;
                    __threadfence();
                    *((volatile unsigned*)&d_tok_gen) = (unsigned)(t + 1);
                }
            }

            // output writes (overlap with gates' remaining work)
            float* orow = out + (size_t)t * B_ * V_ + (size_t)b0h * V_;
            for (int i = tid; i < 8 * V_ / 4; i += 256) {
                const int bi = i >> 8;
                float4 v4 = *(const float4*)&z2s[bi][(i & 255) * 4];
                const float l = lse_s[bi];
                v4.x -= l; v4.y -= l; v4.z -= l; v4.w -= l;
                *(float4*)&orow[i * 4] = v4;
            }
            stage_barrier();
        }
    }
}

// ---------------------------------------------------------------------------
// kernel_launch: 4 graph nodes (init + 2 transposes + persistent loop)
// ---------------------------------------------------------------------------
extern "C" void kernel_launch(void* const* d_in, const int* in_sizes, int n_in,
                              void* d_out, int out_size)
{
    const float* input   = (const float*)d_in[0];
    const float* onehots = (const float*)d_in[1];
    const float* Wh   = (const float*)d_in[4];
    const float* bh   = (const float*)d_in[5];
    const float* Wc   = (const float*)d_in[6];
    const float* bc   = (const float*)d_in[7];
    const float* W_ih = (const float*)d_in[8];
    const float* W_hh = (const float*)d_in[9];
    const float* b_ih = (const float*)d_in[10];
    const float* b_hh = (const float*)d_in[11];
    const float* W1   = (const float*)d_in[12];
    const float* b1   = (const float*)d_in[13];
    const float* W2   = (const float*)d_in[14];
    const float* b2   = (const float*)d_in[15];
    float* out = (float*)d_out;

    init_kernel<<<B_, 256>>>(input, onehots, Wh, bh, Wc, bc, b_ih, b_hh);
    transpose_w2_kernel<<<GEN_, 256>>>(W2);
    {
        dim3 g(H4_ / 32, V_ / 32);
        transpose_wih_kernel<<<g, 256>>>(W_ih);
    }
    lstm_pipeline_kernel<<<NTOT, 256>>>(W_hh, W1, b1, b2, out);
}